// round 2
// baseline (speedup 1.0000x reference)
#include <cuda_runtime.h>
#include <math.h>

// Problem constants
#define NB   256      // batch rows
#define DD   2048     // hidden dim
#define II   5504     // mlp dim
#define KSEL 128      // top-k selected rows

// ---------------- scratch (device globals; no allocation allowed) ----------
__device__ float g_scores[NB];
__device__ int   g_sel[KSEL];
__device__ float g_x [KSEL*DD];
__device__ float g_h [KSEL*DD];
__device__ float g_v [KSEL*DD];
__device__ float g_x2[KSEL*DD];
__device__ float g_h2[KSEL*DD];
__device__ float g_g [KSEL*II];
__device__ float g_u [KSEL*II];
__device__ float g_a [KSEL*II];

// ---------------- router scores ---------------------------------------------
__global__ __launch_bounds__(256) void scores_kernel(
    const float* __restrict__ hs, const float* __restrict__ rw,
    const float* __restrict__ rb)
{
    int b = blockIdx.x;
    const float* row = hs + (size_t)b * DD;
    float s = 0.f;
    for (int i = threadIdx.x; i < DD; i += 256) s += row[i] * rw[i];
    __shared__ float sm[256];
    sm[threadIdx.x] = s; __syncthreads();
    for (int st = 128; st > 0; st >>= 1) {
        if (threadIdx.x < st) sm[threadIdx.x] += sm[threadIdx.x + st];
        __syncthreads();
    }
    if (threadIdx.x == 0) g_scores[b] = sm[0] + rb[0];
}

// ---------------- top-k selection (rank by O(n^2) compare; n=256) -----------
__global__ __launch_bounds__(256) void topk_kernel()
{
    __shared__ float s[NB];
    __shared__ int   flag[NB];
    int t = threadIdx.x;
    s[t] = g_scores[t];
    __syncthreads();
    float mine = s[t];
    int rank = 0;
    for (int j = 0; j < NB; j++) {
        float o = s[j];
        // JAX top_k tie-break: equal values -> smaller index ranks higher
        if (o > mine || (o == mine && j < t)) rank++;
    }
    flag[t] = (rank < KSEL) ? 1 : 0;
    __syncthreads();
    if (t == 0) {
        int c = 0;
        for (int j = 0; j < NB; j++) if (flag[j]) g_sel[c++] = j;
    }
}

// ---------------- passthrough copy of full hidden_states to output ----------
__global__ __launch_bounds__(256) void copy_kernel(
    const float4* __restrict__ src, float4* __restrict__ dst, int n4)
{
    for (int i = blockIdx.x * blockDim.x + threadIdx.x; i < n4;
         i += gridDim.x * blockDim.x)
        dst[i] = src[i];
}

// ---------------- gather + RMSNorm (also plain RMSNorm) ---------------------
// gather=1: src row = hidden[g_sel[blk]] ; writes raw row to x_out and normed to h_out
// gather=0: src row = src[blk]           ; writes normed row to h_out only
__global__ __launch_bounds__(256) void gather_rms_kernel(
    const float* __restrict__ src_full, const float* __restrict__ w,
    float* __restrict__ x_out, float* __restrict__ h_out, int gather)
{
    int r = blockIdx.x;
    const float* src = gather ? (src_full + (size_t)g_sel[r] * DD)
                              : (src_full + (size_t)r * DD);
    float vals[8]; float ss = 0.f;
    #pragma unroll
    for (int j = 0; j < 8; j++) {
        int i = j * 256 + threadIdx.x;
        float v = src[i]; vals[j] = v; ss += v * v;
    }
    __shared__ float sm[256];
    sm[threadIdx.x] = ss; __syncthreads();
    for (int st = 128; st > 0; st >>= 1) {
        if (threadIdx.x < st) sm[threadIdx.x] += sm[threadIdx.x + st];
        __syncthreads();
    }
    float inv = rsqrtf(sm[0] * (1.0f / (float)DD) + 1e-6f);
    #pragma unroll
    for (int j = 0; j < 8; j++) {
        int i = j * 256 + threadIdx.x;
        if (x_out) x_out[(size_t)r * DD + i] = vals[j];
        h_out[(size_t)r * DD + i] = vals[j] * inv * w[i];
    }
}

// ---------------- SGEMM: C[M=128, N] = A[128, K] @ W[K, N] (+epilogue) ------
// MODE 0: C = acc (+ bias[n] if bias)          -> v = h@wv + bv ; g/u GEMMs
// MODE 1: C = addend + acc                     -> x2 = x + v@wo
// MODE 2: C[g_sel[m]*N + n] = addend + acc     -> scatter: out = x2 + a@w_down
template<int BN, int TN, int MODE>
__global__ __launch_bounds__(256) void sgemm_kernel(
    const float* __restrict__ A, const float* __restrict__ W,
    const float* __restrict__ bias, const float* __restrict__ addend,
    float* __restrict__ C, int N, int K)
{
    constexpr int BM = 64, BK = 16, TM = 4;
    constexpr int TX = BN / TN;      // 16
    __shared__ float As[BK][BM];
    __shared__ float Bs[BK][BN];
    const int tid = threadIdx.x;
    const int tx = tid % TX, ty = tid / TX;   // ty in [0,16)
    const int bm0 = blockIdx.y * BM, bn0 = blockIdx.x * BN;

    float acc[TM][TN];
    #pragma unroll
    for (int m = 0; m < TM; m++)
        #pragma unroll
        for (int n = 0; n < TN; n++) acc[m][n] = 0.f;

    const int ar = tid >> 2, ac4 = tid & 3;   // A tile: 64 rows x 4 float4

    for (int k0 = 0; k0 < K; k0 += BK) {
        float4 av = *(const float4*)(A + (size_t)(bm0 + ar) * K + k0 + ac4 * 4);
        As[ac4 * 4 + 0][ar] = av.x;
        As[ac4 * 4 + 1][ar] = av.y;
        As[ac4 * 4 + 2][ar] = av.z;
        As[ac4 * 4 + 3][ar] = av.w;
        #pragma unroll
        for (int i = tid; i < BK * BN / 4; i += 256) {
            int r = i / (BN / 4), c = i % (BN / 4);
            float4 bv4 = *(const float4*)(W + (size_t)(k0 + r) * N + bn0 + c * 4);
            *(float4*)&Bs[r][c * 4] = bv4;
        }
        __syncthreads();
        #pragma unroll
        for (int k = 0; k < BK; k++) {
            float a_[TM], b_[TN];
            #pragma unroll
            for (int m = 0; m < TM; m++) a_[m] = As[k][ty * TM + m];
            #pragma unroll
            for (int n = 0; n < TN; n++) b_[n] = Bs[k][tx * TN + n];
            #pragma unroll
            for (int m = 0; m < TM; m++)
                #pragma unroll
                for (int n = 0; n < TN; n++) acc[m][n] += a_[m] * b_[n];
        }
        __syncthreads();
    }

    #pragma unroll
    for (int m = 0; m < TM; m++) {
        int gm = bm0 + ty * TM + m;
        #pragma unroll
        for (int n = 0; n < TN; n++) {
            int gn = bn0 + tx * TN + n;
            float vv = acc[m][n];
            if (MODE == 0) {
                if (bias) vv += bias[gn];
                C[(size_t)gm * N + gn] = vv;
            } else if (MODE == 1) {
                C[(size_t)gm * N + gn] = addend[(size_t)gm * N + gn] + vv;
            } else {
                C[(size_t)g_sel[gm] * N + gn] = addend[(size_t)gm * N + gn] + vv;
            }
        }
    }
}

// ---------------- silu(g) * u ------------------------------------------------
__global__ __launch_bounds__(256) void silu_mul_kernel()
{
    int i = blockIdx.x * blockDim.x + threadIdx.x;
    if (i < KSEL * II) {
        float g = g_g[i];
        g_a[i] = g / (1.f + expf(-g)) * g_u[i];
    }
}

// ---------------- launch -----------------------------------------------------
extern "C" void kernel_launch(void* const* d_in, const int* in_sizes, int n_in,
                              void* d_out, int out_size)
{
    const float* hs  = (const float*)d_in[0];
    const float* rw  = (const float*)d_in[3];
    const float* rb  = (const float*)d_in[4];
    const float* ln1 = (const float*)d_in[5];
    const float* ln2 = (const float*)d_in[6];
    // wq/bq/wk/bk (d_in[7..10]) are dead: softmax over a single key == 1, so o == v
    const float* wv  = (const float*)d_in[11];
    const float* bv  = (const float*)d_in[12];
    const float* wo  = (const float*)d_in[13];
    const float* wg  = (const float*)d_in[14];
    const float* wu  = (const float*)d_in[15];
    const float* wd  = (const float*)d_in[16];
    float* out = (float*)d_out;

    float *px, *ph, *pv, *px2, *ph2, *pa;
    cudaGetSymbolAddress((void**)&px,  g_x);
    cudaGetSymbolAddress((void**)&ph,  g_h);
    cudaGetSymbolAddress((void**)&pv,  g_v);
    cudaGetSymbolAddress((void**)&px2, g_x2);
    cudaGetSymbolAddress((void**)&ph2, g_h2);
    cudaGetSymbolAddress((void**)&pa,  g_a);
    float *pg, *pu;
    cudaGetSymbolAddress((void**)&pg,  g_g);
    cudaGetSymbolAddress((void**)&pu,  g_u);

    scores_kernel<<<NB, 256>>>(hs, rw, rb);
    topk_kernel<<<1, 256>>>();
    copy_kernel<<<256, 256>>>((const float4*)hs, (float4*)out, (NB * DD) / 4);
    gather_rms_kernel<<<KSEL, 256>>>(hs, ln1, px, ph, 1);
    // v = h @ wv + bv
    sgemm_kernel<32, 2, 0><<<dim3(DD / 32, KSEL / 64), 256>>>(ph, wv, bv, nullptr, pv, DD, DD);
    // x2 = x + v @ wo
    sgemm_kernel<32, 2, 1><<<dim3(DD / 32, KSEL / 64), 256>>>(pv, wo, nullptr, px, px2, DD, DD);
    // h2 = rms(x2, ln2)
    gather_rms_kernel<<<KSEL, 256>>>(px2, ln2, nullptr, ph2, 0);
    // g = h2 @ w_gate ; u = h2 @ w_up
    sgemm_kernel<64, 4, 0><<<dim3(II / 64, KSEL / 64), 256>>>(ph2, wg, nullptr, nullptr, pg, II, DD);
    sgemm_kernel<64, 4, 0><<<dim3(II / 64, KSEL / 64), 256>>>(ph2, wu, nullptr, nullptr, pu, II, DD);
    // a = silu(g) * u
    silu_mul_kernel<<<(KSEL * II + 255) / 256, 256>>>();
    // out[sel[m]] = x2 + a @ w_down
    sgemm_kernel<32, 2, 2><<<dim3(DD / 32, KSEL / 64), 256>>>(pa, wd, nullptr, px2, out, DD, II);
}

// round 5
// speedup vs baseline: 6.0771x; 6.0771x over previous
#include <cuda_runtime.h>
#include <cuda_fp16.h>
#include <math.h>

#define NB   256
#define DD   2048
#define II   5504
#define KSEL 128

// ---------------- scratch (device globals) ----------------------------------
__device__ float  g_scores[NB];
__device__ int    g_sel[KSEL];
__device__ float  g_x [KSEL*DD];     // gathered selected rows (fp32, residual)
__device__ float  g_x2[KSEL*DD];     // post-attention residual (fp32)
__device__ __half g_h16[KSEL*DD];    // rms(x)      fp16 (GEMM A)
__device__ __half g_v16[KSEL*DD];    // v = h@wv+bv fp16 (GEMM A)
__device__ __half g_h2 [KSEL*DD];    // rms(x2)     fp16 (GEMM A)
__device__ __half g_a16[KSEL*II];    // silu(g)*u   fp16 (GEMM A)
#define SBELEMS (4*KSEL*II)          // max split scratch: 4 x 128 x 5504
__device__ float  g_sb0[SBELEMS];
__device__ float  g_sb1[SBELEMS];

// ---------------- router scores ---------------------------------------------
__global__ __launch_bounds__(256) void scores_kernel(
    const float* __restrict__ hs, const float* __restrict__ rw,
    const float* __restrict__ rb)
{
    int b = blockIdx.x;
    const float* row = hs + (size_t)b * DD;
    float s = 0.f;
    for (int i = threadIdx.x; i < DD; i += 256) s += row[i] * rw[i];
    __shared__ float sm[256];
    sm[threadIdx.x] = s; __syncthreads();
    for (int st = 128; st > 0; st >>= 1) {
        if (threadIdx.x < st) sm[threadIdx.x] += sm[threadIdx.x + st];
        __syncthreads();
    }
    if (threadIdx.x == 0) g_scores[b] = sm[0] + rb[0];
}

// ---------------- top-k selection -------------------------------------------
__global__ __launch_bounds__(256) void topk_kernel()
{
    __shared__ float s[NB];
    __shared__ int   flag[NB];
    int t = threadIdx.x;
    s[t] = g_scores[t];
    __syncthreads();
    float mine = s[t];
    int rank = 0;
    for (int j = 0; j < NB; j++) {
        float o = s[j];
        if (o > mine || (o == mine && j < t)) rank++;
    }
    flag[t] = (rank < KSEL) ? 1 : 0;
    __syncthreads();
    if (t == 0) {
        int c = 0;
        for (int j = 0; j < NB; j++) if (flag[j]) g_sel[c++] = j;
    }
}

// ---------------- passthrough copy ------------------------------------------
__global__ __launch_bounds__(256) void copy_kernel(
    const float4* __restrict__ src, float4* __restrict__ dst, int n4)
{
    for (int i = blockIdx.x * blockDim.x + threadIdx.x; i < n4;
         i += gridDim.x * blockDim.x)
        dst[i] = src[i];
}

// ---------------- gather + RMSNorm -> fp16 ----------------------------------
__global__ __launch_bounds__(256) void gather_rms_kernel(
    const float* __restrict__ src_full, const float* __restrict__ w,
    float* __restrict__ x_out, __half* __restrict__ h_out, int gather)
{
    int r = blockIdx.x;
    const float* src = gather ? (src_full + (size_t)g_sel[r] * DD)
                              : (src_full + (size_t)r * DD);
    float vals[8]; float ss = 0.f;
    #pragma unroll
    for (int j = 0; j < 8; j++) {
        int i = j * 256 + threadIdx.x;
        float v = src[i]; vals[j] = v; ss += v * v;
    }
    __shared__ float sm[256];
    sm[threadIdx.x] = ss; __syncthreads();
    for (int st = 128; st > 0; st >>= 1) {
        if (threadIdx.x < st) sm[threadIdx.x] += sm[threadIdx.x + st];
        __syncthreads();
    }
    float inv = rsqrtf(sm[0] * (1.0f / (float)DD) + 1e-6f);
    #pragma unroll
    for (int j = 0; j < 8; j++) {
        int i = j * 256 + threadIdx.x;
        if (x_out) x_out[(size_t)r * DD + i] = vals[j];
        h_out[(size_t)r * DD + i] = __float2half_rn(vals[j] * inv * w[i]);
    }
}

// ---------------- mma.sync helpers ------------------------------------------
__device__ __forceinline__ unsigned smaddr(const void* p) {
    return (unsigned)__cvta_generic_to_shared(p);
}
__device__ __forceinline__ void ldsm4(unsigned a, unsigned& r0, unsigned& r1,
                                      unsigned& r2, unsigned& r3) {
    asm volatile("ldmatrix.sync.aligned.m8n8.x4.shared.b16 {%0,%1,%2,%3}, [%4];"
                 : "=r"(r0), "=r"(r1), "=r"(r2), "=r"(r3) : "r"(a));
}
__device__ __forceinline__ void ldsm4t(unsigned a, unsigned& r0, unsigned& r1,
                                       unsigned& r2, unsigned& r3) {
    asm volatile("ldmatrix.sync.aligned.m8n8.x4.trans.shared.b16 {%0,%1,%2,%3}, [%4];"
                 : "=r"(r0), "=r"(r1), "=r"(r2), "=r"(r3) : "r"(a));
}
__device__ __forceinline__ void mma16816(float* c, const unsigned* a,
                                         const unsigned* b) {
    asm volatile("mma.sync.aligned.m16n8k16.row.col.f32.f16.f16.f32 "
                 "{%0,%1,%2,%3}, {%4,%5,%6,%7}, {%8,%9}, {%0,%1,%2,%3};"
                 : "+f"(c[0]), "+f"(c[1]), "+f"(c[2]), "+f"(c[3])
                 : "r"(a[0]), "r"(a[1]), "r"(a[2]), "r"(a[3]),
                   "r"(b[0]), "r"(b[1]));
}

// ---------------- HGEMM: Csplit[z] = A[128,Kslice] @ W[Kslice,N] -------------
// A: fp16 [128, K] row-major. W: fp32 [K, N] row-major (converted in-kernel).
// grid = (N/128, splits). 256 threads. 3-stage smem pipeline.
#define A_PITCH 40                  // halves (32 data + 8 pad) -> 80B rows
#define B_PITCH 136                 // halves (128 data + 8 pad) -> 272B rows
#define A_STAGE (128*A_PITCH)
#define B_STAGE (32*B_PITCH)
#define SMEM_BYTES (3*(A_STAGE+B_STAGE)*(int)sizeof(__half))

__global__ __launch_bounds__(256) void hgemm_kernel(
    const __half* __restrict__ A, const float* __restrict__ W,
    float* __restrict__ Csplit, int N, int K, int kPerSplit)
{
    extern __shared__ char smraw[];
    __half* As = (__half*)smraw;
    __half* Bs = As + 3 * A_STAGE;

    const int tid  = threadIdx.x;
    const int lane = tid & 31, warp = tid >> 5;
    const int wm = warp & 3, wn = warp >> 2;          // 4 M-warps x 2 N-warps
    const int n0 = blockIdx.x * 128;
    const int kb = blockIdx.y * kPerSplit;
    const int ke = min(kb + kPerSplit, K);
    const int nch = (ke - kb + 31) >> 5;

    const int arow = tid >> 1, acol = (tid & 1) << 4;   // A tile 128x32 halves
    const int brow = tid >> 3, bcol = (tid & 7) << 4;   // B tile 32x128 floats

    float acc[2][8][4];
    #pragma unroll
    for (int i = 0; i < 2; i++)
        #pragma unroll
        for (int j = 0; j < 8; j++)
            #pragma unroll
            for (int q = 0; q < 4; q++) acc[i][j][q] = 0.f;

    uint4  ra0, ra1;
    float4 rb0, rb1, rb2, rb3;

    auto ldg = [&](int c) {
        int k0 = kb + (c << 5);
        bool av = (k0 + acol) < ke;                    // ke is multiple of 16
        const uint4* ap = (const uint4*)(A + (size_t)arow * K +
                                         (av ? (k0 + acol) : kb));
        uint4 za = make_uint4(0, 0, 0, 0);
        ra0 = av ? ap[0] : za;
        ra1 = av ? ap[1] : za;
        int krow = k0 + brow;
        bool bv = krow < ke;
        const float4* bp = (const float4*)(W + (size_t)(bv ? krow : kb) * N +
                                           n0 + bcol);
        float4 zf = make_float4(0, 0, 0, 0);
        rb0 = bv ? bp[0] : zf; rb1 = bv ? bp[1] : zf;
        rb2 = bv ? bp[2] : zf; rb3 = bv ? bp[3] : zf;
    };

    auto sts = [&](int s) {
        __half* a = As + s * A_STAGE + arow * A_PITCH + acol;
        *(uint4*)a       = ra0;
        *(uint4*)(a + 8) = ra1;
        __align__(16) __half t[16];
        t[0]=__float2half_rn(rb0.x); t[1]=__float2half_rn(rb0.y);
        t[2]=__float2half_rn(rb0.z); t[3]=__float2half_rn(rb0.w);
        t[4]=__float2half_rn(rb1.x); t[5]=__float2half_rn(rb1.y);
        t[6]=__float2half_rn(rb1.z); t[7]=__float2half_rn(rb1.w);
        t[8]=__float2half_rn(rb2.x); t[9]=__float2half_rn(rb2.y);
        t[10]=__float2half_rn(rb2.z); t[11]=__float2half_rn(rb2.w);
        t[12]=__float2half_rn(rb3.x); t[13]=__float2half_rn(rb3.y);
        t[14]=__float2half_rn(rb3.z); t[15]=__float2half_rn(rb3.w);
        __half* b = Bs + s * B_STAGE + brow * B_PITCH + bcol;
        *(uint4*)b       = ((uint4*)t)[0];
        *(uint4*)(b + 8) = ((uint4*)t)[1];
    };

    auto mmastage = [&](int s) {
        #pragma unroll
        for (int kk = 0; kk < 2; kk++) {               // two k16 per 32-chunk
            unsigned af[2][4];
            #pragma unroll
            for (int at = 0; at < 2; at++) {
                int r = wm * 32 + at * 16 + (lane & 7) + ((lane >> 3) & 1) * 8;
                int c = kk * 16 + (lane >> 4) * 8;
                ldsm4(smaddr(As + s * A_STAGE + r * A_PITCH + c),
                      af[at][0], af[at][1], af[at][2], af[at][3]);
            }
            unsigned bf[8][2];
            #pragma unroll
            for (int nq = 0; nq < 4; nq++) {
                int r = kk * 16 + ((lane >> 3) & 1) * 8 + (lane & 7);
                int c = wn * 64 + nq * 16 + (lane >> 4) * 8;
                unsigned r0, r1, r2, r3;
                ldsm4t(smaddr(Bs + s * B_STAGE + r * B_PITCH + c), r0, r1, r2, r3);
                bf[nq*2][0] = r0; bf[nq*2][1] = r1;
                bf[nq*2+1][0] = r2; bf[nq*2+1][1] = r3;
            }
            #pragma unroll
            for (int at = 0; at < 2; at++)
                #pragma unroll
                for (int nb = 0; nb < 8; nb++)
                    mma16816(acc[at][nb], af[at], bf[nb]);
        }
    };

    ldg(0); sts(0);
    if (nch > 1) { ldg(1); sts(1); }
    for (int c = 0; c < nch; c++) {
        __syncthreads();
        bool pf = (c + 2) < nch;
        if (pf) ldg(c + 2);
        mmastage(c % 3);
        if (pf) sts((c + 2) % 3);
    }

    float* Cs = Csplit + (size_t)blockIdx.y * 128 * N;
    int g = lane >> 2, q = lane & 3;
    #pragma unroll
    for (int at = 0; at < 2; at++) {
        int r = wm * 32 + at * 16 + g;
        #pragma unroll
        for (int nb = 0; nb < 8; nb++) {
            int cix = n0 + wn * 64 + nb * 8 + 2 * q;
            *(float2*)&Cs[(size_t)r * N + cix] =
                make_float2(acc[at][nb][0], acc[at][nb][1]);
            *(float2*)&Cs[(size_t)(r + 8) * N + cix] =
                make_float2(acc[at][nb][2], acc[at][nb][3]);
        }
    }
}

// ---------------- split-K reductions with fused epilogues --------------------
template<int SPLITS>
__global__ __launch_bounds__(256) void red_bias_h_kernel(
    const float* __restrict__ S, const float* __restrict__ bias,
    __half* __restrict__ out, int N)
{
    int i = blockIdx.x * 256 + threadIdx.x;
    int tot = KSEL * N / 4;
    if (i >= tot) return;
    const float4* S4 = (const float4*)S;
    size_t stride = (size_t)KSEL * N / 4;
    float4 s = S4[i];
    #pragma unroll
    for (int z = 1; z < SPLITS; z++) {
        float4 t = S4[z * stride + i];
        s.x += t.x; s.y += t.y; s.z += t.z; s.w += t.w;
    }
    float4 b = ((const float4*)bias)[i % (N / 4)];
    s.x += b.x; s.y += b.y; s.z += b.z; s.w += b.w;
    __half2* o = (__half2*)out;
    o[2*i]     = __floats2half2_rn(s.x, s.y);
    o[2*i + 1] = __floats2half2_rn(s.z, s.w);
}

template<int SPLITS>
__global__ __launch_bounds__(256) void red_resid_kernel(
    const float* __restrict__ S, const float* __restrict__ X,
    float* __restrict__ out, int N)
{
    int i = blockIdx.x * 256 + threadIdx.x;
    int tot = KSEL * N / 4;
    if (i >= tot) return;
    const float4* S4 = (const float4*)S;
    size_t stride = (size_t)KSEL * N / 4;
    float4 s = S4[i];
    #pragma unroll
    for (int z = 1; z < SPLITS; z++) {
        float4 t = S4[z * stride + i];
        s.x += t.x; s.y += t.y; s.z += t.z; s.w += t.w;
    }
    float4 x = ((const float4*)X)[i];
    s.x += x.x; s.y += x.y; s.z += x.z; s.w += x.w;
    ((float4*)out)[i] = s;
}

template<int SPLITS>
__global__ __launch_bounds__(256) void red_silu_kernel(
    const float* __restrict__ Sg, const float* __restrict__ Su,
    __half* __restrict__ out, int N)
{
    int i = blockIdx.x * 256 + threadIdx.x;
    int tot = KSEL * N / 4;
    if (i >= tot) return;
    const float4* G4 = (const float4*)Sg;
    const float4* U4 = (const float4*)Su;
    size_t stride = (size_t)KSEL * N / 4;
    float4 g = G4[i], u = U4[i];
    #pragma unroll
    for (int z = 1; z < SPLITS; z++) {
        float4 t = G4[z * stride + i];
        g.x += t.x; g.y += t.y; g.z += t.z; g.w += t.w;
        float4 v = U4[z * stride + i];
        u.x += v.x; u.y += v.y; u.z += v.z; u.w += v.w;
    }
    float a0 = g.x / (1.f + expf(-g.x)) * u.x;
    float a1 = g.y / (1.f + expf(-g.y)) * u.y;
    float a2 = g.z / (1.f + expf(-g.z)) * u.z;
    float a3 = g.w / (1.f + expf(-g.w)) * u.w;
    __half2* o = (__half2*)out;
    o[2*i]     = __floats2half2_rn(a0, a1);
    o[2*i + 1] = __floats2half2_rn(a2, a3);
}

template<int SPLITS>
__global__ __launch_bounds__(256) void red_scatter_kernel(
    const float* __restrict__ S, const float* __restrict__ X2,
    float* __restrict__ out)   // out: [256][2048]
{
    int i = blockIdx.x * 256 + threadIdx.x;
    int tot = KSEL * DD / 4;
    if (i >= tot) return;
    const float4* S4 = (const float4*)S;
    size_t stride = (size_t)KSEL * DD / 4;
    float4 s = S4[i];
    #pragma unroll
    for (int z = 1; z < SPLITS; z++) {
        float4 t = S4[z * stride + i];
        s.x += t.x; s.y += t.y; s.z += t.z; s.w += t.w;
    }
    float4 x = ((const float4*)X2)[i];
    s.x += x.x; s.y += x.y; s.z += x.z; s.w += x.w;
    int row = i / (DD / 4), c4 = i % (DD / 4);
    ((float4*)out)[(size_t)g_sel[row] * (DD / 4) + c4] = s;
}

// ---------------- launch -----------------------------------------------------
extern "C" void kernel_launch(void* const* d_in, const int* in_sizes, int n_in,
                              void* d_out, int out_size)
{
    const float* hs  = (const float*)d_in[0];
    const float* rw  = (const float*)d_in[3];
    const float* rb  = (const float*)d_in[4];
    const float* ln1 = (const float*)d_in[5];
    const float* ln2 = (const float*)d_in[6];
    // wq/bq/wk/bk (d_in[7..10]) are dead: softmax over a single key == 1 -> o == v
    const float* wv  = (const float*)d_in[11];
    const float* bv  = (const float*)d_in[12];
    const float* wo  = (const float*)d_in[13];
    const float* wg  = (const float*)d_in[14];
    const float* wu  = (const float*)d_in[15];
    const float* wd  = (const float*)d_in[16];
    float* out = (float*)d_out;

    float *px, *px2, *psb0, *psb1;
    __half *ph16, *pv16, *ph2, *pa16;
    cudaGetSymbolAddress((void**)&px,   g_x);
    cudaGetSymbolAddress((void**)&px2,  g_x2);
    cudaGetSymbolAddress((void**)&ph16, g_h16);
    cudaGetSymbolAddress((void**)&pv16, g_v16);
    cudaGetSymbolAddress((void**)&ph2,  g_h2);
    cudaGetSymbolAddress((void**)&pa16, g_a16);
    cudaGetSymbolAddress((void**)&psb0, g_sb0);
    cudaGetSymbolAddress((void**)&psb1, g_sb1);

    cudaFuncSetAttribute(hgemm_kernel,
                         cudaFuncAttributeMaxDynamicSharedMemorySize, SMEM_BYTES);

    scores_kernel<<<NB, 256>>>(hs, rw, rb);
    topk_kernel<<<1, 256>>>();
    copy_kernel<<<256, 256>>>((const float4*)hs, (float4*)out, (NB * DD) / 4);
    gather_rms_kernel<<<KSEL, 256>>>(hs, ln1, px, ph16, 1);

    const int rdD = (KSEL * DD / 4 + 255) / 256;   // 256 blocks
    const int rdI = (KSEL * II / 4 + 255) / 256;   // 688 blocks

    // v = h @ wv + bv             (K=2048, N=2048, 8 splits of 256)
    hgemm_kernel<<<dim3(DD/128, 8), 256, SMEM_BYTES>>>(ph16, wv, psb0, DD, DD, 256);
    red_bias_h_kernel<8><<<rdD, 256>>>(psb0, bv, pv16, DD);
    // x2 = x + v @ wo             (K=2048, N=2048, 8 splits)
    hgemm_kernel<<<dim3(DD/128, 8), 256, SMEM_BYTES>>>(pv16, wo, psb0, DD, DD, 256);
    red_resid_kernel<8><<<rdD, 256>>>(psb0, px, px2, DD);
    // h2 = rms(x2)
    gather_rms_kernel<<<KSEL, 256>>>(px2, ln2, nullptr, ph2, 0);
    // g = h2 @ w_gate ; u = h2 @ w_up   (K=2048, N=5504, 4 splits of 512)
    hgemm_kernel<<<dim3(II/128, 4), 256, SMEM_BYTES>>>(ph2, wg, psb0, II, DD, 512);
    hgemm_kernel<<<dim3(II/128, 4), 256, SMEM_BYTES>>>(ph2, wu, psb1, II, DD, 512);
    red_silu_kernel<4><<<rdI, 256>>>(psb0, psb1, pa16, II);
    // out[sel] = x2 + a @ w_down  (K=5504, N=2048, 8 splits of 688)
    hgemm_kernel<<<dim3(DD/128, 8), 256, SMEM_BYTES>>>(pa16, wd, psb0, DD, II, 688);
    red_scatter_kernel<8><<<rdD, 256>>>(psb0, px2, out);
}

// round 6
// speedup vs baseline: 6.7548x; 1.1115x over previous
#include <cuda_runtime.h>
#include <cuda_fp16.h>
#include <math.h>

#define NB   256
#define DD   2048
#define II   5504
#define KSEL 128

// ---------------- scratch (device globals) ----------------------------------
__device__ float  g_scores[NB];
__device__ int    g_sel[KSEL];
__device__ float  g_x [KSEL*DD];     // gathered selected rows (fp32, residual)
__device__ float  g_x2[KSEL*DD];     // post-attention residual (fp32)
__device__ __half g_h16[KSEL*DD];    // rms(x)      fp16 (GEMM A)
__device__ __half g_v16[KSEL*DD];    // v = h@wv+bv fp16 (GEMM A)
__device__ __half g_h2 [KSEL*DD];    // rms(x2)     fp16 (GEMM A)
__device__ __half g_a16[KSEL*II];    // silu(g)*u   fp16 (GEMM A)
#define SBELEMS (8*KSEL*II)          // split scratch
__device__ float  g_sb0[SBELEMS];
__device__ float  g_sb1[SBELEMS];

// ---------------- router scores ---------------------------------------------
__global__ __launch_bounds__(256) void scores_kernel(
    const float* __restrict__ hs, const float* __restrict__ rw,
    const float* __restrict__ rb)
{
    int b = blockIdx.x;
    const float4* row = (const float4*)(hs + (size_t)b * DD);
    const float4* w4  = (const float4*)rw;
    float s = 0.f;
    #pragma unroll
    for (int j = 0; j < 2; j++) {
        int i = j * 256 + threadIdx.x;
        float4 v = row[i], w = w4[i];
        s += v.x * w.x + v.y * w.y + v.z * w.z + v.w * w.w;
    }
    __shared__ float sm[256];
    sm[threadIdx.x] = s; __syncthreads();
    for (int st = 128; st > 0; st >>= 1) {
        if (threadIdx.x < st) sm[threadIdx.x] += sm[threadIdx.x + st];
        __syncthreads();
    }
    if (threadIdx.x == 0) g_scores[b] = sm[0] + rb[0];
}

// ---------------- top-k selection -------------------------------------------
__global__ __launch_bounds__(256) void topk_kernel()
{
    __shared__ float s[NB];
    __shared__ int   flag[NB];
    int t = threadIdx.x;
    s[t] = g_scores[t];
    __syncthreads();
    float mine = s[t];
    int rank = 0;
    for (int j = 0; j < NB; j++) {
        float o = s[j];
        if (o > mine || (o == mine && j < t)) rank++;
    }
    flag[t] = (rank < KSEL) ? 1 : 0;
    __syncthreads();
    if (t == 0) {
        int c = 0;
        for (int j = 0; j < NB; j++) if (flag[j]) g_sel[c++] = j;
    }
}

// ---------------- passthrough copy ------------------------------------------
__global__ __launch_bounds__(256) void copy_kernel(
    const float4* __restrict__ src, float4* __restrict__ dst, int n4)
{
    for (int i = blockIdx.x * blockDim.x + threadIdx.x; i < n4;
         i += gridDim.x * blockDim.x)
        dst[i] = src[i];
}

// ---------------- gather + RMSNorm -> fp16 (512 thr, float4) ----------------
__global__ __launch_bounds__(512) void gather_rms_kernel(
    const float* __restrict__ src_full, const float* __restrict__ w,
    float* __restrict__ x_out, __half* __restrict__ h_out, int gather)
{
    int r = blockIdx.x;
    int t = threadIdx.x;                       // 0..511, one float4 each
    const float* src = gather ? (src_full + (size_t)g_sel[r] * DD)
                              : (src_full + (size_t)r * DD);
    float4 v = ((const float4*)src)[t];
    float ss = v.x * v.x + v.y * v.y + v.z * v.z + v.w * v.w;
    __shared__ float sm[512];
    sm[t] = ss; __syncthreads();
    for (int st = 256; st > 0; st >>= 1) {
        if (t < st) sm[t] += sm[t + st];
        __syncthreads();
    }
    float inv = rsqrtf(sm[0] * (1.0f / (float)DD) + 1e-6f);
    if (x_out) ((float4*)(x_out + (size_t)r * DD))[t] = v;
    float4 wv = ((const float4*)w)[t];
    __half2* o = (__half2*)(h_out + (size_t)r * DD);
    o[2*t]     = __floats2half2_rn(v.x * inv * wv.x, v.y * inv * wv.y);
    o[2*t + 1] = __floats2half2_rn(v.z * inv * wv.z, v.w * inv * wv.w);
}

// ---------------- mma.sync helpers ------------------------------------------
__device__ __forceinline__ unsigned smaddr(const void* p) {
    return (unsigned)__cvta_generic_to_shared(p);
}
__device__ __forceinline__ void ldsm4(unsigned a, unsigned& r0, unsigned& r1,
                                      unsigned& r2, unsigned& r3) {
    asm volatile("ldmatrix.sync.aligned.m8n8.x4.shared.b16 {%0,%1,%2,%3}, [%4];"
                 : "=r"(r0), "=r"(r1), "=r"(r2), "=r"(r3) : "r"(a));
}
__device__ __forceinline__ void ldsm4t(unsigned a, unsigned& r0, unsigned& r1,
                                       unsigned& r2, unsigned& r3) {
    asm volatile("ldmatrix.sync.aligned.m8n8.x4.trans.shared.b16 {%0,%1,%2,%3}, [%4];"
                 : "=r"(r0), "=r"(r1), "=r"(r2), "=r"(r3) : "r"(a));
}
__device__ __forceinline__ void mma16816(float* c, const unsigned* a,
                                         const unsigned* b) {
    asm volatile("mma.sync.aligned.m16n8k16.row.col.f32.f16.f16.f32 "
                 "{%0,%1,%2,%3}, {%4,%5,%6,%7}, {%8,%9}, {%0,%1,%2,%3};"
                 : "+f"(c[0]), "+f"(c[1]), "+f"(c[2]), "+f"(c[3])
                 : "r"(a[0]), "r"(a[1]), "r"(a[2]), "r"(a[3]),
                   "r"(b[0]), "r"(b[1]));
}

// ---------------- HGEMM: Csplit[z] = A[128,Kslice] @ W[Kslice,N] -------------
// A: fp16 [128,K] row-major. W: fp32 [K,N] row-major (converted in-kernel).
// grid = (N/128, splits, nW). 256 threads. 4-stage smem + 2-deep reg pipeline.
#define A_PITCH 40                  // halves (32 data + 8 pad)
#define B_PITCH 136                 // halves (128 data + 8 pad)
#define A_STAGE (128*A_PITCH)
#define B_STAGE (32*B_PITCH)
#define NSTAGE  4
#define SMEM_BYTES (NSTAGE*(A_STAGE+B_STAGE)*(int)sizeof(__half))

struct Pref {
    uint4  ra0, ra1;
    float4 rb0, rb1, rb2, rb3;
};

__global__ __launch_bounds__(256) void hgemm_kernel(
    const __half* __restrict__ A,
    const float* __restrict__ W0, const float* __restrict__ W1,
    float* __restrict__ C0, float* __restrict__ C1,
    int N, int K, int kPerSplit)
{
    extern __shared__ char smraw[];
    __half* As = (__half*)smraw;
    __half* Bs = As + NSTAGE * A_STAGE;

    const float* W = blockIdx.z ? W1 : W0;
    float* C       = blockIdx.z ? C1 : C0;

    const int tid  = threadIdx.x;
    const int lane = tid & 31, warp = tid >> 5;
    const int wm = warp & 3, wn = warp >> 2;          // 4 M-warps x 2 N-warps
    const int n0 = blockIdx.x * 128;
    const int kb = blockIdx.y * kPerSplit;
    const int ke = min(kb + kPerSplit, K);
    const int nch = (ke - kb + 31) >> 5;

    const int arow = tid >> 1, acol = (tid & 1) << 4;   // A tile 128x32 halves
    const int brow = tid >> 3, bcol = (tid & 7) << 4;   // B tile 32x128 floats

    float acc[2][8][4];
    #pragma unroll
    for (int i = 0; i < 2; i++)
        #pragma unroll
        for (int j = 0; j < 8; j++)
            #pragma unroll
            for (int q = 0; q < 4; q++) acc[i][j][q] = 0.f;

    auto ldg = [&](Pref& p, int c) {
        int k0 = kb + (c << 5);
        bool av = (k0 + acol) < ke;
        const uint4* ap = (const uint4*)(A + (size_t)arow * K +
                                         (av ? (k0 + acol) : kb));
        uint4 za = make_uint4(0, 0, 0, 0);
        p.ra0 = av ? ap[0] : za;
        p.ra1 = av ? ap[1] : za;
        int krow = k0 + brow;
        bool bv = krow < ke;
        const float4* bp = (const float4*)(W + (size_t)(bv ? krow : kb) * N +
                                           n0 + bcol);
        float4 zf = make_float4(0, 0, 0, 0);
        p.rb0 = bv ? bp[0] : zf; p.rb1 = bv ? bp[1] : zf;
        p.rb2 = bv ? bp[2] : zf; p.rb3 = bv ? bp[3] : zf;
    };

    auto sts = [&](const Pref& p, int s) {
        __half* a = As + s * A_STAGE + arow * A_PITCH + acol;
        *(uint4*)a       = p.ra0;
        *(uint4*)(a + 8) = p.ra1;
        __align__(16) __half t[16];
        t[0]=__float2half_rn(p.rb0.x); t[1]=__float2half_rn(p.rb0.y);
        t[2]=__float2half_rn(p.rb0.z); t[3]=__float2half_rn(p.rb0.w);
        t[4]=__float2half_rn(p.rb1.x); t[5]=__float2half_rn(p.rb1.y);
        t[6]=__float2half_rn(p.rb1.z); t[7]=__float2half_rn(p.rb1.w);
        t[8]=__float2half_rn(p.rb2.x); t[9]=__float2half_rn(p.rb2.y);
        t[10]=__float2half_rn(p.rb2.z); t[11]=__float2half_rn(p.rb2.w);
        t[12]=__float2half_rn(p.rb3.x); t[13]=__float2half_rn(p.rb3.y);
        t[14]=__float2half_rn(p.rb3.z); t[15]=__float2half_rn(p.rb3.w);
        __half* b = Bs + s * B_STAGE + brow * B_PITCH + bcol;
        *(uint4*)b       = ((uint4*)t)[0];
        *(uint4*)(b + 8) = ((uint4*)t)[1];
    };

    auto mmastage = [&](int s) {
        #pragma unroll
        for (int kk = 0; kk < 2; kk++) {
            unsigned af[2][4];
            #pragma unroll
            for (int at = 0; at < 2; at++) {
                int r = wm * 32 + at * 16 + (lane & 7) + ((lane >> 3) & 1) * 8;
                int c = kk * 16 + (lane >> 4) * 8;
                ldsm4(smaddr(As + s * A_STAGE + r * A_PITCH + c),
                      af[at][0], af[at][1], af[at][2], af[at][3]);
            }
            unsigned bf[8][2];
            #pragma unroll
            for (int nq = 0; nq < 4; nq++) {
                int r = kk * 16 + ((lane >> 3) & 1) * 8 + (lane & 7);
                int c = wn * 64 + nq * 16 + (lane >> 4) * 8;
                unsigned r0, r1, r2, r3;
                ldsm4t(smaddr(Bs + s * B_STAGE + r * B_PITCH + c), r0, r1, r2, r3);
                bf[nq*2][0] = r0;   bf[nq*2][1] = r1;
                bf[nq*2+1][0] = r2; bf[nq*2+1][1] = r3;
            }
            #pragma unroll
            for (int at = 0; at < 2; at++)
                #pragma unroll
                for (int nb = 0; nb < 8; nb++)
                    mma16816(acc[at][nb], af[at], bf[nb]);
        }
    };

    // Prologue: stage chunks 0,1 into smem; hold chunks 2,3 in registers.
    Pref P0, P1;
    ldg(P0, 0); sts(P0, 0);
    if (nch > 1) { ldg(P1, 1); sts(P1, 1); }
    if (nch > 2) ldg(P0, 2);
    if (nch > 3) ldg(P1, 3);

    // Mainloop: sync; STS(c+2); LDG(c+4); MMA(c).  LDG->STS distance = 2 iters.
    int c = 0;
    while (c < nch) {
        __syncthreads();
        if (c + 2 < nch) sts(P0, (c + 2) & 3);
        if (c + 4 < nch) ldg(P0, c + 4);
        mmastage(c & 3);
        c++;
        if (c >= nch) break;
        __syncthreads();
        if (c + 2 < nch) sts(P1, (c + 2) & 3);
        if (c + 4 < nch) ldg(P1, c + 4);
        mmastage(c & 3);
        c++;
    }

    float* Cs = C + (size_t)blockIdx.y * 128 * N;
    int g = lane >> 2, q = lane & 3;
    #pragma unroll
    for (int at = 0; at < 2; at++) {
        int r = wm * 32 + at * 16 + g;
        #pragma unroll
        for (int nb = 0; nb < 8; nb++) {
            int cix = n0 + wn * 64 + nb * 8 + 2 * q;
            *(float2*)&Cs[(size_t)r * N + cix] =
                make_float2(acc[at][nb][0], acc[at][nb][1]);
            *(float2*)&Cs[(size_t)(r + 8) * N + cix] =
                make_float2(acc[at][nb][2], acc[at][nb][3]);
        }
    }
}

// ---------------- split-K reductions with fused epilogues --------------------
template<int SPLITS>
__global__ __launch_bounds__(256) void red_bias_h_kernel(
    const float* __restrict__ S, const float* __restrict__ bias,
    __half* __restrict__ out, int N)
{
    int i = blockIdx.x * 256 + threadIdx.x;
    int tot = KSEL * N / 4;
    if (i >= tot) return;
    const float4* S4 = (const float4*)S;
    size_t stride = (size_t)KSEL * N / 4;
    float4 s = S4[i];
    #pragma unroll
    for (int z = 1; z < SPLITS; z++) {
        float4 t = S4[z * stride + i];
        s.x += t.x; s.y += t.y; s.z += t.z; s.w += t.w;
    }
    float4 b = ((const float4*)bias)[i % (N / 4)];
    s.x += b.x; s.y += b.y; s.z += b.z; s.w += b.w;
    __half2* o = (__half2*)out;
    o[2*i]     = __floats2half2_rn(s.x, s.y);
    o[2*i + 1] = __floats2half2_rn(s.z, s.w);
}

template<int SPLITS>
__global__ __launch_bounds__(256) void red_resid_kernel(
    const float* __restrict__ S, const float* __restrict__ X,
    float* __restrict__ out, int N)
{
    int i = blockIdx.x * 256 + threadIdx.x;
    int tot = KSEL * N / 4;
    if (i >= tot) return;
    const float4* S4 = (const float4*)S;
    size_t stride = (size_t)KSEL * N / 4;
    float4 s = S4[i];
    #pragma unroll
    for (int z = 1; z < SPLITS; z++) {
        float4 t = S4[z * stride + i];
        s.x += t.x; s.y += t.y; s.z += t.z; s.w += t.w;
    }
    float4 x = ((const float4*)X)[i];
    s.x += x.x; s.y += x.y; s.z += x.z; s.w += x.w;
    ((float4*)out)[i] = s;
}

template<int SPLITS>
__global__ __launch_bounds__(256) void red_silu_kernel(
    const float* __restrict__ Sg, const float* __restrict__ Su,
    __half* __restrict__ out, int N)
{
    int i = blockIdx.x * 256 + threadIdx.x;
    int tot = KSEL * N / 4;
    if (i >= tot) return;
    const float4* G4 = (const float4*)Sg;
    const float4* U4 = (const float4*)Su;
    size_t stride = (size_t)KSEL * N / 4;
    float4 g = G4[i], u = U4[i];
    #pragma unroll
    for (int z = 1; z < SPLITS; z++) {
        float4 t = G4[z * stride + i];
        g.x += t.x; g.y += t.y; g.z += t.z; g.w += t.w;
        float4 v = U4[z * stride + i];
        u.x += v.x; u.y += v.y; u.z += v.z; u.w += v.w;
    }
    float a0 = g.x / (1.f + expf(-g.x)) * u.x;
    float a1 = g.y / (1.f + expf(-g.y)) * u.y;
    float a2 = g.z / (1.f + expf(-g.z)) * u.z;
    float a3 = g.w / (1.f + expf(-g.w)) * u.w;
    __half2* o = (__half2*)out;
    o[2*i]     = __floats2half2_rn(a0, a1);
    o[2*i + 1] = __floats2half2_rn(a2, a3);
}

template<int SPLITS>
__global__ __launch_bounds__(256) void red_scatter_kernel(
    const float* __restrict__ S, const float* __restrict__ X2,
    float* __restrict__ out)   // out: [256][2048]
{
    int i = blockIdx.x * 256 + threadIdx.x;
    int tot = KSEL * DD / 4;
    if (i >= tot) return;
    const float4* S4 = (const float4*)S;
    size_t stride = (size_t)KSEL * DD / 4;
    float4 s = S4[i];
    #pragma unroll
    for (int z = 1; z < SPLITS; z++) {
        float4 t = S4[z * stride + i];
        s.x += t.x; s.y += t.y; s.z += t.z; s.w += t.w;
    }
    float4 x = ((const float4*)X2)[i];
    s.x += x.x; s.y += x.y; s.z += x.z; s.w += x.w;
    int row = i / (DD / 4), c4 = i % (DD / 4);
    ((float4*)out)[(size_t)g_sel[row] * (DD / 4) + c4] = s;
}

// ---------------- launch -----------------------------------------------------
extern "C" void kernel_launch(void* const* d_in, const int* in_sizes, int n_in,
                              void* d_out, int out_size)
{
    const float* hs  = (const float*)d_in[0];
    const float* rw  = (const float*)d_in[3];
    const float* rb  = (const float*)d_in[4];
    const float* ln1 = (const float*)d_in[5];
    const float* ln2 = (const float*)d_in[6];
    // wq/bq/wk/bk (d_in[7..10]) are dead: softmax over a single key == 1 -> o == v
    const float* wv  = (const float*)d_in[11];
    const float* bv  = (const float*)d_in[12];
    const float* wo  = (const float*)d_in[13];
    const float* wg  = (const float*)d_in[14];
    const float* wu  = (const float*)d_in[15];
    const float* wd  = (const float*)d_in[16];
    float* out = (float*)d_out;

    float *px, *px2, *psb0, *psb1;
    __half *ph16, *pv16, *ph2, *pa16;
    cudaGetSymbolAddress((void**)&px,   g_x);
    cudaGetSymbolAddress((void**)&px2,  g_x2);
    cudaGetSymbolAddress((void**)&ph16, g_h16);
    cudaGetSymbolAddress((void**)&pv16, g_v16);
    cudaGetSymbolAddress((void**)&ph2,  g_h2);
    cudaGetSymbolAddress((void**)&pa16, g_a16);
    cudaGetSymbolAddress((void**)&psb0, g_sb0);
    cudaGetSymbolAddress((void**)&psb1, g_sb1);

    cudaFuncSetAttribute(hgemm_kernel,
                         cudaFuncAttributeMaxDynamicSharedMemorySize, SMEM_BYTES);

    scores_kernel<<<NB, 256>>>(hs, rw, rb);
    topk_kernel<<<1, 256>>>();
    gather_rms_kernel<<<KSEL, 512>>>(hs, ln1, px, ph16, 1);

    const int rdD = (KSEL * DD / 4 + 255) / 256;   // 256 blocks
    const int rdI = (KSEL * II / 4 + 255) / 256;   // 688 blocks

    // v = h @ wv + bv             (K=2048, N=2048, 8 splits of 256)
    hgemm_kernel<<<dim3(DD/128, 8, 1), 256, SMEM_BYTES>>>(
        ph16, wv, wv, psb0, psb0, DD, DD, 256);
    red_bias_h_kernel<8><<<rdD, 256>>>(psb0, bv, pv16, DD);
    // x2 = x + v @ wo             (K=2048, N=2048, 8 splits)
    hgemm_kernel<<<dim3(DD/128, 8, 1), 256, SMEM_BYTES>>>(
        pv16, wo, wo, psb0, psb0, DD, DD, 256);
    red_resid_kernel<8><<<rdD, 256>>>(psb0, px, px2, DD);
    // h2 = rms(x2)
    gather_rms_kernel<<<KSEL, 512>>>(px2, ln2, nullptr, ph2, 0);
    // g = h2 @ w_gate ; u = h2 @ w_up   (one launch, K=2048, N=5504, 4 splits)
    hgemm_kernel<<<dim3(II/128, 4, 2), 256, SMEM_BYTES>>>(
        ph2, wg, wu, psb0, psb1, II, DD, 512);
    red_silu_kernel<4><<<rdI, 256>>>(psb0, psb1, pa16, II);
    // out[sel] = x2 + a @ w_down  (K=5504, N=2048, 8 splits of 688)
    hgemm_kernel<<<dim3(DD/128, 8, 1), 256, SMEM_BYTES>>>(
        pa16, wd, wd, psb0, psb0, DD, II, 688);
    copy_kernel<<<256, 256>>>((const float4*)hs, (float4*)out, (NB * DD) / 4);
    red_scatter_kernel<8><<<rdD, 256>>>(psb0, px2, out);
}